// round 12
// baseline (speedup 1.0000x reference)
#include <cuda_runtime.h>

#define W 512
#define H 512
#define BATCH 32
#define IMG (H * W)
#define NTOT (BATCH * IMG)
#define HS 16
#define NSTRIP (H / HS)
#define FULLM 0xffffffffu
#define NLOSSBLK (NSTRIP * BATCH)

// Static device scratch (allocation-free rule): two ping-pong buffers holding
// both tensors (pred at offset 0, target at offset NTOT).
__device__ float g_b0[2 * NTOT];
__device__ float g_b1[2 * NTOT];
__device__ double g_acc;
__device__ unsigned int g_done;

__device__ __forceinline__ float4 ld4(const float* p) {
    return *reinterpret_cast<const float4*>(p);
}
__device__ __forceinline__ float2 ld2(const float* p) {
    return *reinterpret_cast<const float2*>(p);
}
__device__ __forceinline__ float4 f4all(float v) { return make_float4(v, v, v, v); }

__global__ void zero_acc_k() { g_acc = 0.0; g_done = 0u; }

// ---------------------------------------------------------------------------
// One soft-skeletonize iteration:
//   m = minpool3x3(x) (pad +inf); M = maxpool3x3(m) (pad -inf);
//   x' = relu(x - relu(M - m))
// FLOAT2 lanes: each lane owns 2 cols; warp covers 64 cols; 128-thread block
// covers 256 cols (2 blocks per image width). Halved per-thread rolling state
// (~40 regs) -> ~12 blocks/SM residency to hide DRAM latency.
// ---------------------------------------------------------------------------
__global__ void __launch_bounds__(128) skel_iter(
    const float* __restrict__ extA, const float* __restrict__ extB,
    int srcSel, int dstSel)
{
    const float PINF = __int_as_float(0x7f800000);
    const float NINF = __int_as_float(0xff800000);
    int lane = threadIdx.x & 31;
    int warp = threadIdx.x >> 5;
    int strip = blockIdx.x >> 1;
    int chalf = blockIdx.x & 1;
    int b = blockIdx.y;
    int t = blockIdx.z;

    const float* src;
    if (srcSel == 0)      src = (t == 0 ? extA : extB);
    else if (srcSel == 1) src = g_b0 + (size_t)t * NTOT;
    else                  src = g_b1 + (size_t)t * NTOT;
    float* dst = (dstSel == 1 ? g_b0 : g_b1) + (size_t)t * NTOT;

    const float* sp = src + (size_t)b * IMG;
    float* dp = dst + (size_t)b * IMG;

    int cbase = chalf * 256 + warp * 64 + lane * 2;
    bool leftEdge = (cbase == 0);
    bool rightEdge = (cbase + 2 == W);
    int r0 = strip * HS;

    // Rolling state (per-lane, float2 view)
    float2 x1, x2;              // input history rows s-1, s-2
    float2 rm1, rm2;            // row-min history
    float rl1, rl2, rr1, rr2;   // halo row-min history (col cbase-1 / cbase+2)
    float2 m1;                  // min-pool output at row s-2
    float2 q1, q2;              // row-max(m) history

    x1 = x2 = make_float2(PINF, PINF);
    rm1 = rm2 = make_float2(PINF, PINF);
    rl1 = rl2 = rr1 = rr2 = PINF;
    m1 = make_float2(NINF, NINF);
    q1 = q2 = make_float2(NINF, NINF);

    const float* rowp = sp + (size_t)(r0 - 2) * W + cbase;
    float* orowp = dp + (size_t)r0 * W + cbase;

    #pragma unroll 4
    for (int s = r0 - 2; s <= r0 + HS + 1; ++s) {
        // ---- load row s (+inf outside image)
        float2 v;
        float hlx = PINF, hly = PINF, hrx = PINF, hry = PINF;
        if (s >= 0 && s < H) {
            v = ld2(rowp);
            if (lane == 0 && !leftEdge)  { float2 h = ld2(rowp - 2); hlx = h.x; hly = h.y; }
            if (lane == 31 && !rightEdge){ float2 h = ld2(rowp + 2); hrx = h.x; hry = h.y; }
        } else {
            v = make_float2(PINF, PINF);
        }
        rowp += W;

        // ---- horizontal min (row s)
        float lf = __shfl_up_sync(FULLM, v.y, 1);
        float rt = __shfl_down_sync(FULLM, v.x, 1);
        if (lane == 0)  lf = hly;    // col cbase-1
        if (lane == 31) rt = hrx;    // col cbase+2
        float tmn = fminf(v.x, v.y);
        float2 rm0;
        rm0.x = fminf(lf, tmn);
        rm0.y = fminf(tmn, rt);
        float rl0 = fminf(fminf(hlx, hly), v.x);   // row-min at col cbase-1 (lane0)
        float rr0 = fminf(fminf(v.y, hrx), hry);   // row-min at col cbase+2 (lane31)

        // ---- vertical min -> m at row s-1
        float2 m0;
        m0.x = fminf(fminf(rm0.x, rm1.x), rm2.x);
        m0.y = fminf(fminf(rm0.y, rm1.y), rm2.y);
        float mL = fminf(fminf(rl0, rl1), rl2);
        float mR = fminf(fminf(rr0, rr1), rr2);
        int mrow = s - 1;
        if (mrow < 0 || mrow >= H) { m0 = make_float2(NINF, NINF); mL = NINF; mR = NINF; }

        // ---- horizontal max of m (row s-1)
        float mlf = __shfl_up_sync(FULLM, m0.y, 1);
        float mrt = __shfl_down_sync(FULLM, m0.x, 1);
        if (lane == 0)  mlf = leftEdge  ? NINF : mL;
        if (lane == 31) mrt = rightEdge ? NINF : mR;
        float tmx = fmaxf(m0.x, m0.y);
        float2 q0;
        q0.x = fmaxf(mlf, tmx);
        q0.y = fmaxf(tmx, mrt);

        // ---- vertical max -> M at row s-2; out = relu(x - relu(M - m))
        int orow = s - 2;
        if (orow >= r0) {
            float Mx = fmaxf(fmaxf(q0.x, q1.x), q2.x);
            float My = fmaxf(fmaxf(q0.y, q1.y), q2.y);
            float2 o;
            o.x = fmaxf(x2.x - fmaxf(Mx - m1.x, 0.0f), 0.0f);
            o.y = fmaxf(x2.y - fmaxf(My - m1.y, 0.0f), 0.0f);
            *reinterpret_cast<float2*>(orowp) = o;
            orowp += W;
        }

        // ---- shift rolling windows
        x2 = x1; x1 = v;
        rm2 = rm1; rm1 = rm0;
        rl2 = rl1; rl1 = rl0;
        rr2 = rr1; rr1 = rr0;
        m1 = m0;
        q2 = q1; q1 = q0;
    }
}

__device__ __forceinline__ float pixel_loss(float a, float bv, float na, float nb) {
    float ds = a - bv;
    float l = 0.6f * ds * ds;
    bool ona = a > 0.5f, onb = bv > 0.5f;
    bool ea = (na == 2.0f) && ona;
    bool eb = (nb == 2.0f) && onb;
    if (ea != eb) l += 0.2f;   // (ep_p - ep_t)^2 is 1 iff they differ
    bool ca = (na >= 4.0f) && ona;
    bool cb = (nb >= 4.0f) && onb;
    if (ca != cb) l += 0.2f;
    return l;
}

// Final stage: 3x3 sum-pool (zero pad) over both skeletons (in g_b0),
// endpoint/crossing booleans, weighted squared diffs, global reduction.
// Last-finishing block writes the output scalar (no separate finalize launch).
__global__ void __launch_bounds__(128) loss_k(float* out)
{
    int lane = threadIdx.x & 31;
    int warp = threadIdx.x >> 5;
    int strip = blockIdx.x;
    int b = blockIdx.y;
    const float* spB = g_b0 + (size_t)b * IMG;
    const float* stB = g_b0 + (size_t)NTOT + (size_t)b * IMG;
    int cbase = warp * 128 + lane * 4;
    bool leftEdge = (cbase == 0);
    bool rightEdge = (cbase + 4 == W);
    int r0 = strip * HS;

    float4 vp1 = f4all(0), vt1 = f4all(0);
    float4 sp1 = f4all(0), sp2 = f4all(0);
    float4 st1 = f4all(0), st2 = f4all(0);
    float acc = 0.0f;

    const float* prp = spB + (size_t)(r0 - 1) * W + cbase;
    const float* trp = stB + (size_t)(r0 - 1) * W + cbase;

    #pragma unroll 3
    for (int s = r0 - 1; s <= r0 + HS; ++s) {
        float4 vp, vt;
        float plw = 0.f, prx = 0.f, tlw = 0.f, trx = 0.f;
        if (s >= 0 && s < H) {
            vp = ld4(prp); vt = ld4(trp);
            if (lane == 0 && !leftEdge)  { plw = prp[-1]; tlw = trp[-1]; }
            if (lane == 31 && !rightEdge){ prx = prp[4];  trx = trp[4];  }
        } else {
            vp = f4all(0);
            vt = f4all(0);
        }
        prp += W; trp += W;

        float lfp = __shfl_up_sync(FULLM, vp.w, 1);
        float rtp = __shfl_down_sync(FULLM, vp.x, 1);
        if (lane == 0)  lfp = plw;
        if (lane == 31) rtp = prx;
        float4 sp0;
        sp0.x = lfp + vp.x + vp.y;
        sp0.y = vp.x + vp.y + vp.z;
        sp0.z = vp.y + vp.z + vp.w;
        sp0.w = vp.z + vp.w + rtp;

        float lft = __shfl_up_sync(FULLM, vt.w, 1);
        float rtt = __shfl_down_sync(FULLM, vt.x, 1);
        if (lane == 0)  lft = tlw;
        if (lane == 31) rtt = trx;
        float4 st0;
        st0.x = lft + vt.x + vt.y;
        st0.y = vt.x + vt.y + vt.z;
        st0.z = vt.y + vt.z + vt.w;
        st0.w = vt.z + vt.w + rtt;

        int orow = s - 1;
        if (orow >= r0) {
            acc += pixel_loss(vp1.x, vt1.x, sp0.x + sp1.x + sp2.x, st0.x + st1.x + st2.x);
            acc += pixel_loss(vp1.y, vt1.y, sp0.y + sp1.y + sp2.y, st0.y + st1.y + st2.y);
            acc += pixel_loss(vp1.z, vt1.z, sp0.z + sp1.z + sp2.z, st0.z + st1.z + st2.z);
            acc += pixel_loss(vp1.w, vt1.w, sp0.w + sp1.w + sp2.w, st0.w + st1.w + st2.w);
        }

        sp2 = sp1; sp1 = sp0;
        st2 = st1; st1 = st0;
        vp1 = vp; vt1 = vt;
    }

    // block reduction (4 warps)
    #pragma unroll
    for (int o = 16; o > 0; o >>= 1)
        acc += __shfl_xor_sync(FULLM, acc, o);
    __shared__ float ws[4];
    if (lane == 0) ws[warp] = acc;
    __syncthreads();
    if (threadIdx.x == 0) {
        atomicAdd(&g_acc, (double)(ws[0] + ws[1] + ws[2] + ws[3]));
        __threadfence();
        unsigned int prev = atomicAdd(&g_done, 1u);
        if (prev == NLOSSBLK - 1) {
            // all blocks' g_acc contributions are visible (fence + atomic order)
            out[0] = (float)(g_acc * (1.0 / (double)NTOT));
        }
    }
}

extern "C" void kernel_launch(void* const* d_in, const int* in_sizes, int n_in,
                              void* d_out, int out_size)
{
    const float* pred = (const float*)d_in[0];
    const float* targ = (const float*)d_in[1];
    float* out = (float*)d_out;

    dim3 git(NSTRIP * 2, BATCH, 2);
    dim3 gls(NSTRIP, BATCH);

    zero_acc_k<<<1, 1>>>();
    // 5 soft-skeletonize iterations, ping-pong: d_in -> b0 -> b1 -> b0 -> b1 -> b0
    skel_iter<<<git, 128>>>(pred, targ, 0, 1);
    skel_iter<<<git, 128>>>(nullptr, nullptr, 1, 2);
    skel_iter<<<git, 128>>>(nullptr, nullptr, 2, 1);
    skel_iter<<<git, 128>>>(nullptr, nullptr, 1, 2);
    skel_iter<<<git, 128>>>(nullptr, nullptr, 2, 1);
    // skeletons now in g_b0; sum-pool + comparisons + weighted MSE + final write
    loss_k<<<gls, 128>>>(out);
}

// round 16
// speedup vs baseline: 1.1087x; 1.1087x over previous
#include <cuda_runtime.h>

#define W 512
#define H 512
#define BATCH 32
#define IMG (H * W)
#define NTOT (BATCH * IMG)
#define HS 16
#define NSTRIP (H / HS)
#define FULLM 0xffffffffu
#define NLOSSBLK (NSTRIP * BATCH)

// Static device scratch (allocation-free rule): two ping-pong buffers holding
// both tensors (pred at offset 0, target at offset NTOT).
__device__ float g_b0[2 * NTOT];
__device__ float g_b1[2 * NTOT];
__device__ double g_acc;
__device__ unsigned int g_done;

__device__ __forceinline__ float4 ld4(const float* p) {
    return *reinterpret_cast<const float4*>(p);
}
__device__ __forceinline__ float4 f4all(float v) { return make_float4(v, v, v, v); }

__global__ void zero_acc_k() { g_acc = 0.0; g_done = 0u; }

// ---------------------------------------------------------------------------
// One soft-skeletonize iteration for ONE tensor (R10-validated kernel body):
//   m = minpool3x3(x) (pad +inf); M = maxpool3x3(m) (pad -inf);
//   x' = relu(x - relu(M - m))
// Register-streaming: warp owns 128 cols (4/lane float4), rolling 3-row
// windows, unroll 4. One tensor per launch so the inter-launch ping-pong
// working set (67 MB) stays L2-resident -> iters 2-5 read at L2 latency.
// ---------------------------------------------------------------------------
__global__ void __launch_bounds__(128) skel_iter(
    const float* __restrict__ ext, int t, int srcSel, int dstSel)
{
    const float PINF = __int_as_float(0x7f800000);
    const float NINF = __int_as_float(0xff800000);
    int lane = threadIdx.x & 31;
    int warp = threadIdx.x >> 5;
    int strip = blockIdx.x;
    int b = blockIdx.y;

    const float* src;
    if (srcSel == 0)      src = ext;
    else if (srcSel == 1) src = g_b0 + (size_t)t * NTOT;
    else                  src = g_b1 + (size_t)t * NTOT;
    float* dst = (dstSel == 1 ? g_b0 : g_b1) + (size_t)t * NTOT;

    const float* sp = src + (size_t)b * IMG;
    float* dp = dst + (size_t)b * IMG;

    int cbase = warp * 128 + lane * 4;
    bool leftEdge = (cbase == 0);
    bool rightEdge = (cbase + 4 == W);
    int r0 = strip * HS;

    float4 x1, x2;
    float4 rm0, rm1, rm2;
    float rl1, rl2, rr1, rr2;
    float4 m1;
    float4 q0, q1, q2;

    x1 = x2 = f4all(PINF);
    rm1 = rm2 = f4all(PINF);
    rl1 = rl2 = rr1 = rr2 = PINF;
    m1 = f4all(NINF);
    q1 = q2 = f4all(NINF);

    const float* rowp = sp + (size_t)(r0 - 2) * W + cbase;
    float* orowp = dp + (size_t)r0 * W + cbase;

    #pragma unroll 4
    for (int s = r0 - 2; s <= r0 + HS + 1; ++s) {
        float4 v;
        float hlz = PINF, hlw = PINF, hrx = PINF, hry = PINF;
        if (s >= 0 && s < H) {
            v = ld4(rowp);
            if (lane == 0 && !leftEdge)  { float4 h = ld4(rowp - 4); hlz = h.z; hlw = h.w; }
            if (lane == 31 && !rightEdge){ float4 h = ld4(rowp + 4); hrx = h.x; hry = h.y; }
        } else {
            v = f4all(PINF);
        }
        rowp += W;

        float lf = __shfl_up_sync(FULLM, v.w, 1);
        float rt = __shfl_down_sync(FULLM, v.x, 1);
        if (lane == 0)  lf = hlw;
        if (lane == 31) rt = hrx;
        rm0.x = fminf(fminf(lf,  v.x), v.y);
        rm0.y = fminf(fminf(v.x, v.y), v.z);
        rm0.z = fminf(fminf(v.y, v.z), v.w);
        rm0.w = fminf(fminf(v.z, v.w), rt);
        float rl0 = fminf(fminf(hlz, hlw), v.x);
        float rr0 = fminf(fminf(v.w, hrx), hry);

        float4 m0;
        m0.x = fminf(fminf(rm0.x, rm1.x), rm2.x);
        m0.y = fminf(fminf(rm0.y, rm1.y), rm2.y);
        m0.z = fminf(fminf(rm0.z, rm1.z), rm2.z);
        m0.w = fminf(fminf(rm0.w, rm1.w), rm2.w);
        float mL = fminf(fminf(rl0, rl1), rl2);
        float mR = fminf(fminf(rr0, rr1), rr2);
        int mrow = s - 1;
        if (mrow < 0 || mrow >= H) { m0 = f4all(NINF); mL = NINF; mR = NINF; }

        float mlf = __shfl_up_sync(FULLM, m0.w, 1);
        float mrt = __shfl_down_sync(FULLM, m0.x, 1);
        if (lane == 0)  mlf = leftEdge  ? NINF : mL;
        if (lane == 31) mrt = rightEdge ? NINF : mR;
        q0.x = fmaxf(fmaxf(mlf,  m0.x), m0.y);
        q0.y = fmaxf(fmaxf(m0.x, m0.y), m0.z);
        q0.z = fmaxf(fmaxf(m0.y, m0.z), m0.w);
        q0.w = fmaxf(fmaxf(m0.z, m0.w), mrt);

        int orow = s - 2;
        if (orow >= r0) {
            float Mx = fmaxf(fmaxf(q0.x, q1.x), q2.x);
            float My = fmaxf(fmaxf(q0.y, q1.y), q2.y);
            float Mz = fmaxf(fmaxf(q0.z, q1.z), q2.z);
            float Mw = fmaxf(fmaxf(q0.w, q1.w), q2.w);
            float4 o;
            o.x = fmaxf(x2.x - fmaxf(Mx - m1.x, 0.0f), 0.0f);
            o.y = fmaxf(x2.y - fmaxf(My - m1.y, 0.0f), 0.0f);
            o.z = fmaxf(x2.z - fmaxf(Mz - m1.z, 0.0f), 0.0f);
            o.w = fmaxf(x2.w - fmaxf(Mw - m1.w, 0.0f), 0.0f);
            *reinterpret_cast<float4*>(orowp) = o;
            orowp += W;
        }

        x2 = x1; x1 = v;
        rm2 = rm1; rm1 = rm0;
        rl2 = rl1; rl1 = rl0;
        rr2 = rr1; rr1 = rr0;
        m1 = m0;
        q2 = q1; q1 = q0;
    }
}

__device__ __forceinline__ float pixel_loss(float a, float bv, float na, float nb) {
    float ds = a - bv;
    float l = 0.6f * ds * ds;
    bool ona = a > 0.5f, onb = bv > 0.5f;
    bool ea = (na == 2.0f) && ona;
    bool eb = (nb == 2.0f) && onb;
    if (ea != eb) l += 0.2f;   // (ep_p - ep_t)^2 is 1 iff they differ
    bool ca = (na >= 4.0f) && ona;
    bool cb = (nb >= 4.0f) && onb;
    if (ca != cb) l += 0.2f;
    return l;
}

// Final stage: 3x3 sum-pool (zero pad) over both skeletons (in g_b0),
// endpoint/crossing booleans, weighted squared diffs, global reduction.
// Last-finishing block writes the output scalar (no separate finalize launch).
__global__ void __launch_bounds__(128) loss_k(float* out)
{
    int lane = threadIdx.x & 31;
    int warp = threadIdx.x >> 5;
    int strip = blockIdx.x;
    int b = blockIdx.y;
    const float* spB = g_b0 + (size_t)b * IMG;
    const float* stB = g_b0 + (size_t)NTOT + (size_t)b * IMG;
    int cbase = warp * 128 + lane * 4;
    bool leftEdge = (cbase == 0);
    bool rightEdge = (cbase + 4 == W);
    int r0 = strip * HS;

    float4 vp1 = f4all(0), vt1 = f4all(0);
    float4 sp1 = f4all(0), sp2 = f4all(0);
    float4 st1 = f4all(0), st2 = f4all(0);
    float acc = 0.0f;

    const float* prp = spB + (size_t)(r0 - 1) * W + cbase;
    const float* trp = stB + (size_t)(r0 - 1) * W + cbase;

    #pragma unroll 3
    for (int s = r0 - 1; s <= r0 + HS; ++s) {
        float4 vp, vt;
        float plw = 0.f, prx = 0.f, tlw = 0.f, trx = 0.f;
        if (s >= 0 && s < H) {
            vp = ld4(prp); vt = ld4(trp);
            if (lane == 0 && !leftEdge)  { plw = prp[-1]; tlw = trp[-1]; }
            if (lane == 31 && !rightEdge){ prx = prp[4];  trx = trp[4];  }
        } else {
            vp = f4all(0);
            vt = f4all(0);
        }
        prp += W; trp += W;

        float lfp = __shfl_up_sync(FULLM, vp.w, 1);
        float rtp = __shfl_down_sync(FULLM, vp.x, 1);
        if (lane == 0)  lfp = plw;
        if (lane == 31) rtp = prx;
        float4 sp0;
        sp0.x = lfp + vp.x + vp.y;
        sp0.y = vp.x + vp.y + vp.z;
        sp0.z = vp.y + vp.z + vp.w;
        sp0.w = vp.z + vp.w + rtp;

        float lft = __shfl_up_sync(FULLM, vt.w, 1);
        float rtt = __shfl_down_sync(FULLM, vt.x, 1);
        if (lane == 0)  lft = tlw;
        if (lane == 31) rtt = trx;
        float4 st0;
        st0.x = lft + vt.x + vt.y;
        st0.y = vt.x + vt.y + vt.z;
        st0.z = vt.y + vt.z + vt.w;
        st0.w = vt.z + vt.w + rtt;

        int orow = s - 1;
        if (orow >= r0) {
            acc += pixel_loss(vp1.x, vt1.x, sp0.x + sp1.x + sp2.x, st0.x + st1.x + st2.x);
            acc += pixel_loss(vp1.y, vt1.y, sp0.y + sp1.y + sp2.y, st0.y + st1.y + st2.y);
            acc += pixel_loss(vp1.z, vt1.z, sp0.z + sp1.z + sp2.z, st0.z + st1.z + st2.z);
            acc += pixel_loss(vp1.w, vt1.w, sp0.w + sp1.w + sp2.w, st0.w + st1.w + st2.w);
        }

        sp2 = sp1; sp1 = sp0;
        st2 = st1; st1 = st0;
        vp1 = vp; vt1 = vt;
    }

    // block reduction (4 warps)
    #pragma unroll
    for (int o = 16; o > 0; o >>= 1)
        acc += __shfl_xor_sync(FULLM, acc, o);
    __shared__ float ws[4];
    if (lane == 0) ws[warp] = acc;
    __syncthreads();
    if (threadIdx.x == 0) {
        atomicAdd(&g_acc, (double)(ws[0] + ws[1] + ws[2] + ws[3]));
        __threadfence();
        unsigned int prev = atomicAdd(&g_done, 1u);
        if (prev == NLOSSBLK - 1) {
            // all blocks' g_acc contributions are visible (fence + atomic order)
            out[0] = (float)(g_acc * (1.0 / (double)NTOT));
        }
    }
}

extern "C" void kernel_launch(void* const* d_in, const int* in_sizes, int n_in,
                              void* d_out, int out_size)
{
    const float* pred = (const float*)d_in[0];
    const float* targ = (const float*)d_in[1];
    float* out = (float*)d_out;

    dim3 git(NSTRIP, BATCH);
    dim3 gls(NSTRIP, BATCH);

    zero_acc_k<<<1, 1>>>();
    // Tensor 0: 5 iterations, ping-pong ending in g_b0. One tensor per launch
    // keeps the 67 MB ping-pong set L2-resident across launches.
    skel_iter<<<git, 128>>>(pred, 0, 0, 1);
    skel_iter<<<git, 128>>>(nullptr, 0, 1, 2);
    skel_iter<<<git, 128>>>(nullptr, 0, 2, 1);
    skel_iter<<<git, 128>>>(nullptr, 0, 1, 2);
    skel_iter<<<git, 128>>>(nullptr, 0, 2, 1);
    // Tensor 1: 5 iterations.
    skel_iter<<<git, 128>>>(targ, 1, 0, 1);
    skel_iter<<<git, 128>>>(nullptr, 1, 1, 2);
    skel_iter<<<git, 128>>>(nullptr, 1, 2, 1);
    skel_iter<<<git, 128>>>(nullptr, 1, 1, 2);
    skel_iter<<<git, 128>>>(nullptr, 1, 2, 1);
    // Skeletons in g_b0; sum-pool + comparisons + weighted MSE + final write.
    loss_k<<<gls, 128>>>(out);
}

// round 17
// speedup vs baseline: 1.4000x; 1.2628x over previous
#include <cuda_runtime.h>

#define W 512
#define H 512
#define BATCH 32
#define IMG (H * W)
#define NTOT (BATCH * IMG)
#define HS 16
#define NSTRIP (H / HS)
#define FULLM 0xffffffffu
#define NLOSSBLK (NSTRIP * BATCH)

// Static device scratch (allocation-free rule): two ping-pong buffers holding
// both tensors (pred at offset 0, target at offset NTOT).
__device__ float g_b0[2 * NTOT];
__device__ float g_b1[2 * NTOT];
__device__ double g_acc;
__device__ unsigned int g_done;

// Host-side streams/events for the two parallel per-tensor chains. Created
// once at static-init time (host objects only; no device memory involved).
struct ForkStreams {
    cudaStream_t s1, s2;
    cudaEvent_t eFork, eJoin1, eJoin2;
    ForkStreams() {
        cudaStreamCreateWithFlags(&s1, cudaStreamNonBlocking);
        cudaStreamCreateWithFlags(&s2, cudaStreamNonBlocking);
        cudaEventCreateWithFlags(&eFork,  cudaEventDisableTiming);
        cudaEventCreateWithFlags(&eJoin1, cudaEventDisableTiming);
        cudaEventCreateWithFlags(&eJoin2, cudaEventDisableTiming);
    }
};
static ForkStreams g_fs;

__device__ __forceinline__ float4 ld4(const float* p) {
    return *reinterpret_cast<const float4*>(p);
}
__device__ __forceinline__ float4 f4all(float v) { return make_float4(v, v, v, v); }

__global__ void zero_acc_k() { g_acc = 0.0; g_done = 0u; }

// ---------------------------------------------------------------------------
// One soft-skeletonize iteration for ONE tensor (R10-validated kernel body):
//   m = minpool3x3(x) (pad +inf); M = maxpool3x3(m) (pad -inf);
//   x' = relu(x - relu(M - m))
// Register-streaming: warp owns 128 cols (4/lane float4), rolling 3-row
// windows, unroll 4. One tensor per launch (L2-resident ping-pong set);
// the two tensors' chains run on parallel graph branches.
// ---------------------------------------------------------------------------
__global__ void __launch_bounds__(128) skel_iter(
    const float* __restrict__ ext, int t, int srcSel, int dstSel)
{
    const float PINF = __int_as_float(0x7f800000);
    const float NINF = __int_as_float(0xff800000);
    int lane = threadIdx.x & 31;
    int warp = threadIdx.x >> 5;
    int strip = blockIdx.x;
    int b = blockIdx.y;

    const float* src;
    if (srcSel == 0)      src = ext;
    else if (srcSel == 1) src = g_b0 + (size_t)t * NTOT;
    else                  src = g_b1 + (size_t)t * NTOT;
    float* dst = (dstSel == 1 ? g_b0 : g_b1) + (size_t)t * NTOT;

    const float* sp = src + (size_t)b * IMG;
    float* dp = dst + (size_t)b * IMG;

    int cbase = warp * 128 + lane * 4;
    bool leftEdge = (cbase == 0);
    bool rightEdge = (cbase + 4 == W);
    int r0 = strip * HS;

    float4 x1, x2;
    float4 rm0, rm1, rm2;
    float rl1, rl2, rr1, rr2;
    float4 m1;
    float4 q0, q1, q2;

    x1 = x2 = f4all(PINF);
    rm1 = rm2 = f4all(PINF);
    rl1 = rl2 = rr1 = rr2 = PINF;
    m1 = f4all(NINF);
    q1 = q2 = f4all(NINF);

    const float* rowp = sp + (size_t)(r0 - 2) * W + cbase;
    float* orowp = dp + (size_t)r0 * W + cbase;

    #pragma unroll 4
    for (int s = r0 - 2; s <= r0 + HS + 1; ++s) {
        float4 v;
        float hlz = PINF, hlw = PINF, hrx = PINF, hry = PINF;
        if (s >= 0 && s < H) {
            v = ld4(rowp);
            if (lane == 0 && !leftEdge)  { float4 h = ld4(rowp - 4); hlz = h.z; hlw = h.w; }
            if (lane == 31 && !rightEdge){ float4 h = ld4(rowp + 4); hrx = h.x; hry = h.y; }
        } else {
            v = f4all(PINF);
        }
        rowp += W;

        float lf = __shfl_up_sync(FULLM, v.w, 1);
        float rt = __shfl_down_sync(FULLM, v.x, 1);
        if (lane == 0)  lf = hlw;
        if (lane == 31) rt = hrx;
        rm0.x = fminf(fminf(lf,  v.x), v.y);
        rm0.y = fminf(fminf(v.x, v.y), v.z);
        rm0.z = fminf(fminf(v.y, v.z), v.w);
        rm0.w = fminf(fminf(v.z, v.w), rt);
        float rl0 = fminf(fminf(hlz, hlw), v.x);
        float rr0 = fminf(fminf(v.w, hrx), hry);

        float4 m0;
        m0.x = fminf(fminf(rm0.x, rm1.x), rm2.x);
        m0.y = fminf(fminf(rm0.y, rm1.y), rm2.y);
        m0.z = fminf(fminf(rm0.z, rm1.z), rm2.z);
        m0.w = fminf(fminf(rm0.w, rm1.w), rm2.w);
        float mL = fminf(fminf(rl0, rl1), rl2);
        float mR = fminf(fminf(rr0, rr1), rr2);
        int mrow = s - 1;
        if (mrow < 0 || mrow >= H) { m0 = f4all(NINF); mL = NINF; mR = NINF; }

        float mlf = __shfl_up_sync(FULLM, m0.w, 1);
        float mrt = __shfl_down_sync(FULLM, m0.x, 1);
        if (lane == 0)  mlf = leftEdge  ? NINF : mL;
        if (lane == 31) mrt = rightEdge ? NINF : mR;
        q0.x = fmaxf(fmaxf(mlf,  m0.x), m0.y);
        q0.y = fmaxf(fmaxf(m0.x, m0.y), m0.z);
        q0.z = fmaxf(fmaxf(m0.y, m0.z), m0.w);
        q0.w = fmaxf(fmaxf(m0.z, m0.w), mrt);

        int orow = s - 2;
        if (orow >= r0) {
            float Mx = fmaxf(fmaxf(q0.x, q1.x), q2.x);
            float My = fmaxf(fmaxf(q0.y, q1.y), q2.y);
            float Mz = fmaxf(fmaxf(q0.z, q1.z), q2.z);
            float Mw = fmaxf(fmaxf(q0.w, q1.w), q2.w);
            float4 o;
            o.x = fmaxf(x2.x - fmaxf(Mx - m1.x, 0.0f), 0.0f);
            o.y = fmaxf(x2.y - fmaxf(My - m1.y, 0.0f), 0.0f);
            o.z = fmaxf(x2.z - fmaxf(Mz - m1.z, 0.0f), 0.0f);
            o.w = fmaxf(x2.w - fmaxf(Mw - m1.w, 0.0f), 0.0f);
            *reinterpret_cast<float4*>(orowp) = o;
            orowp += W;
        }

        x2 = x1; x1 = v;
        rm2 = rm1; rm1 = rm0;
        rl2 = rl1; rl1 = rl0;
        rr2 = rr1; rr1 = rr0;
        m1 = m0;
        q2 = q1; q1 = q0;
    }
}

__device__ __forceinline__ float pixel_loss(float a, float bv, float na, float nb) {
    float ds = a - bv;
    float l = 0.6f * ds * ds;
    bool ona = a > 0.5f, onb = bv > 0.5f;
    bool ea = (na == 2.0f) && ona;
    bool eb = (nb == 2.0f) && onb;
    if (ea != eb) l += 0.2f;   // (ep_p - ep_t)^2 is 1 iff they differ
    bool ca = (na >= 4.0f) && ona;
    bool cb = (nb >= 4.0f) && onb;
    if (ca != cb) l += 0.2f;
    return l;
}

// Final stage: 3x3 sum-pool (zero pad) over both skeletons (in g_b0),
// endpoint/crossing booleans, weighted squared diffs, global reduction.
// Last-finishing block writes the output scalar (no separate finalize launch).
__global__ void __launch_bounds__(128) loss_k(float* out)
{
    int lane = threadIdx.x & 31;
    int warp = threadIdx.x >> 5;
    int strip = blockIdx.x;
    int b = blockIdx.y;
    const float* spB = g_b0 + (size_t)b * IMG;
    const float* stB = g_b0 + (size_t)NTOT + (size_t)b * IMG;
    int cbase = warp * 128 + lane * 4;
    bool leftEdge = (cbase == 0);
    bool rightEdge = (cbase + 4 == W);
    int r0 = strip * HS;

    float4 vp1 = f4all(0), vt1 = f4all(0);
    float4 sp1 = f4all(0), sp2 = f4all(0);
    float4 st1 = f4all(0), st2 = f4all(0);
    float acc = 0.0f;

    const float* prp = spB + (size_t)(r0 - 1) * W + cbase;
    const float* trp = stB + (size_t)(r0 - 1) * W + cbase;

    #pragma unroll 3
    for (int s = r0 - 1; s <= r0 + HS; ++s) {
        float4 vp, vt;
        float plw = 0.f, prx = 0.f, tlw = 0.f, trx = 0.f;
        if (s >= 0 && s < H) {
            vp = ld4(prp); vt = ld4(trp);
            if (lane == 0 && !leftEdge)  { plw = prp[-1]; tlw = trp[-1]; }
            if (lane == 31 && !rightEdge){ prx = prp[4];  trx = trp[4];  }
        } else {
            vp = f4all(0);
            vt = f4all(0);
        }
        prp += W; trp += W;

        float lfp = __shfl_up_sync(FULLM, vp.w, 1);
        float rtp = __shfl_down_sync(FULLM, vp.x, 1);
        if (lane == 0)  lfp = plw;
        if (lane == 31) rtp = prx;
        float4 sp0;
        sp0.x = lfp + vp.x + vp.y;
        sp0.y = vp.x + vp.y + vp.z;
        sp0.z = vp.y + vp.z + vp.w;
        sp0.w = vp.z + vp.w + rtp;

        float lft = __shfl_up_sync(FULLM, vt.w, 1);
        float rtt = __shfl_down_sync(FULLM, vt.x, 1);
        if (lane == 0)  lft = tlw;
        if (lane == 31) rtt = trx;
        float4 st0;
        st0.x = lft + vt.x + vt.y;
        st0.y = vt.x + vt.y + vt.z;
        st0.z = vt.y + vt.z + vt.w;
        st0.w = vt.z + vt.w + rtt;

        int orow = s - 1;
        if (orow >= r0) {
            acc += pixel_loss(vp1.x, vt1.x, sp0.x + sp1.x + sp2.x, st0.x + st1.x + st2.x);
            acc += pixel_loss(vp1.y, vt1.y, sp0.y + sp1.y + sp2.y, st0.y + st1.y + st2.y);
            acc += pixel_loss(vp1.z, vt1.z, sp0.z + sp1.z + sp2.z, st0.z + st1.z + st2.z);
            acc += pixel_loss(vp1.w, vt1.w, sp0.w + sp1.w + sp2.w, st0.w + st1.w + st2.w);
        }

        sp2 = sp1; sp1 = sp0;
        st2 = st1; st1 = st0;
        vp1 = vp; vt1 = vt;
    }

    // block reduction (4 warps)
    #pragma unroll
    for (int o = 16; o > 0; o >>= 1)
        acc += __shfl_xor_sync(FULLM, acc, o);
    __shared__ float ws[4];
    if (lane == 0) ws[warp] = acc;
    __syncthreads();
    if (threadIdx.x == 0) {
        atomicAdd(&g_acc, (double)(ws[0] + ws[1] + ws[2] + ws[3]));
        __threadfence();
        unsigned int prev = atomicAdd(&g_done, 1u);
        if (prev == NLOSSBLK - 1) {
            // all blocks' g_acc contributions are visible (fence + atomic order)
            out[0] = (float)(g_acc * (1.0 / (double)NTOT));
        }
    }
}

extern "C" void kernel_launch(void* const* d_in, const int* in_sizes, int n_in,
                              void* d_out, int out_size)
{
    const float* pred = (const float*)d_in[0];
    const float* targ = (const float*)d_in[1];
    float* out = (float*)d_out;

    dim3 git(NSTRIP, BATCH);
    dim3 gls(NSTRIP, BATCH);

    // Root node on the (captured) default stream.
    zero_acc_k<<<1, 1>>>();

    // Fork: both side streams depend on the root.
    cudaEventRecord(g_fs.eFork, 0);
    cudaStreamWaitEvent(g_fs.s1, g_fs.eFork, 0);
    cudaStreamWaitEvent(g_fs.s2, g_fs.eFork, 0);

    // Tensor 0 chain on s1 (ping-pong ending in g_b0).
    skel_iter<<<git, 128, 0, g_fs.s1>>>(pred, 0, 0, 1);
    skel_iter<<<git, 128, 0, g_fs.s1>>>(nullptr, 0, 1, 2);
    skel_iter<<<git, 128, 0, g_fs.s1>>>(nullptr, 0, 2, 1);
    skel_iter<<<git, 128, 0, g_fs.s1>>>(nullptr, 0, 1, 2);
    skel_iter<<<git, 128, 0, g_fs.s1>>>(nullptr, 0, 2, 1);

    // Tensor 1 chain on s2.
    skel_iter<<<git, 128, 0, g_fs.s2>>>(targ, 1, 0, 1);
    skel_iter<<<git, 128, 0, g_fs.s2>>>(nullptr, 1, 1, 2);
    skel_iter<<<git, 128, 0, g_fs.s2>>>(nullptr, 1, 2, 1);
    skel_iter<<<git, 128, 0, g_fs.s2>>>(nullptr, 1, 1, 2);
    skel_iter<<<git, 128, 0, g_fs.s2>>>(nullptr, 1, 2, 1);

    // Join back onto the default stream.
    cudaEventRecord(g_fs.eJoin1, g_fs.s1);
    cudaEventRecord(g_fs.eJoin2, g_fs.s2);
    cudaStreamWaitEvent(0, g_fs.eJoin1, 0);
    cudaStreamWaitEvent(0, g_fs.eJoin2, 0);

    // Skeletons in g_b0; sum-pool + comparisons + weighted MSE + final write.
    loss_k<<<gls, 128>>>(out);
}